// round 8
// baseline (speedup 1.0000x reference)
#include <cuda_runtime.h>
#include <math.h>

#define D_MODEL 2048
#define SEQ     2048
#define NBATCH  2
#define NH      32
#define NKV     8
#define HD      64
#define NREP    4
#define KVW     (NKV*HD)        // 512
#define MROWS   (NBATCH*SEQ)    // 4096
#define OUT_ELEMS (MROWS * D_MODEL)

// scratch (static device globals — no allocations allowed)
__device__ float g_q[(size_t)MROWS * D_MODEL];
__device__ float g_k[(size_t)MROWS * KVW];
__device__ float g_v[(size_t)MROWS * KVW];
__device__ float g_attn[(size_t)MROWS * D_MODEL];

// ---------------------------------------------------------------------------
// GEMM: C[M,N] = A[M,K] @ B[N,K]^T (verified function-equal to naive)
// ---------------------------------------------------------------------------
__global__ __launch_bounds__(256, 2)
void sgemm_abt(const float* __restrict__ A, const float* __restrict__ B,
               float* __restrict__ C, int N, int K)
{
    __shared__ float As[16][132];
    __shared__ float Bs[16][132];
    const int tid = threadIdx.x;
    const int tx = tid & 15, ty = tid >> 4;
    const float* Ab = A + (size_t)blockIdx.y * 128 * K;
    const float* Bb = B + (size_t)blockIdx.x * 128 * K;

    float acc[8][8];
    #pragma unroll
    for (int i = 0; i < 8; i++)
        #pragma unroll
        for (int j = 0; j < 8; j++) acc[i][j] = 0.f;

    for (int k0 = 0; k0 < K; k0 += 16) {
        #pragma unroll
        for (int l = 0; l < 2; l++) {
            int idx = tid + l * 256;
            int row = idx >> 2;
            int c4  = (idx & 3) * 4;
            float4 va = *(const float4*)(Ab + (size_t)row * K + k0 + c4);
            float4 vb = *(const float4*)(Bb + (size_t)row * K + k0 + c4);
            As[c4+0][row] = va.x; As[c4+1][row] = va.y;
            As[c4+2][row] = va.z; As[c4+3][row] = va.w;
            Bs[c4+0][row] = vb.x; Bs[c4+1][row] = vb.y;
            Bs[c4+2][row] = vb.z; Bs[c4+3][row] = vb.w;
        }
        __syncthreads();
        #pragma unroll
        for (int k = 0; k < 16; k++) {
            float a[8], b[8];
            *(float4*)&a[0] = *(const float4*)&As[k][ty*8];
            *(float4*)&a[4] = *(const float4*)&As[k][ty*8+4];
            *(float4*)&b[0] = *(const float4*)&Bs[k][tx*8];
            *(float4*)&b[4] = *(const float4*)&Bs[k][tx*8+4];
            #pragma unroll
            for (int i = 0; i < 8; i++)
                #pragma unroll
                for (int j = 0; j < 8; j++)
                    acc[i][j] = fmaf(a[i], b[j], acc[i][j]);
        }
        __syncthreads();
    }

    float* Cb = C + (size_t)(blockIdx.y*128 + ty*8) * N + blockIdx.x*128 + tx*8;
    #pragma unroll
    for (int i = 0; i < 8; i++) {
        *(float4*)(Cb + (size_t)i*N)     = make_float4(acc[i][0],acc[i][1],acc[i][2],acc[i][3]);
        *(float4*)(Cb + (size_t)i*N + 4) = make_float4(acc[i][4],acc[i][5],acc[i][6],acc[i][7]);
    }
}

// ---------------------------------------------------------------------------
// SIGN-FLIPPED interleaved RoPE (rotation by -theta), in-place.
// pair i of each head: (2i,2i+1), angle = pos * 10000^(-2i/64)
//   out[2i]   =  x[2i]*cos + x[2i+1]*sin
//   out[2i+1] = -x[2i]*sin + x[2i+1]*cos
// ---------------------------------------------------------------------------
__global__ void rope_kernel(float* __restrict__ buf, int width)
{
    int idx = blockIdx.x * blockDim.x + threadIdx.x;
    int ppr = width >> 1;
    if (idx >= MROWS * ppr) return;
    int m = idx / ppr;
    int p = idx - m * ppr;
    int i = p & 31;
    int s = m & (SEQ - 1);
    float inv = powf(10000.0f, -((float)(2*i)) / 64.0f);
    float ang = (float)s * inv;
    float c, sn;
    sincosf(ang, &c, &sn);
    sn = -sn;                              // SIGN FLIP (rotation by -theta)
    float* el = buf + (size_t)m * width + 2*p;
    float xr = el[0], xi = el[1];
    el[0] = xr * c - xi * sn;
    el[1] = xr * sn + xi * c;
}

// ---------------------------------------------------------------------------
// Flash attention, causal, GQA (verified function-equal to naive)
// ---------------------------------------------------------------------------
#define FA_TP   68
#define FA_BUF  (64*FA_TP)
#define FA_SMEM ((4*FA_BUF + 3*64) * 4)

__global__ __launch_bounds__(256)
void flash_attn(const float* __restrict__ Q, const float* __restrict__ K,
                const float* __restrict__ V, float* __restrict__ O)
{
    extern __shared__ float sm[];
    float* Qt = sm;
    float* Kt = sm + FA_BUF;
    float* Vs = sm + 2*FA_BUF;
    float* S  = sm + 3*FA_BUF;
    float* mS = sm + 4*FA_BUF;
    float* lS = mS + 64;
    float* aS = lS + 64;

    const int qt = blockIdx.x, h = blockIdx.y, b = blockIdx.z;
    const int kh = h >> 2;
    const int tid = threadIdx.x;
    const int tx = tid & 15, ty = tid >> 4;
    const float scale = 0.125f;

    for (int e = tid; e < 64*64; e += 256) {
        int r = e >> 6, d = e & 63;
        Qt[d*FA_TP + r] = Q[((size_t)(b*SEQ) + qt*64 + r) * D_MODEL + h*HD + d];
    }
    if (tid < 64) { mS[tid] = -INFINITY; lS[tid] = 0.f; }

    float o[4][4];
    #pragma unroll
    for (int i = 0; i < 4; i++)
        #pragma unroll
        for (int j = 0; j < 4; j++) o[i][j] = 0.f;

    for (int kt = 0; kt <= qt; kt++) {
        for (int e = tid; e < 64*64; e += 256) {
            int c = e >> 6, d = e & 63;
            size_t gi = ((size_t)(b*SEQ) + kt*64 + c) * KVW + kh*HD + d;
            Kt[d*FA_TP + c] = K[gi];
            Vs[c*FA_TP + d] = V[gi];
        }
        __syncthreads();

        float s[4][4];
        #pragma unroll
        for (int i = 0; i < 4; i++)
            #pragma unroll
            for (int j = 0; j < 4; j++) s[i][j] = 0.f;

        #pragma unroll 8
        for (int kk = 0; kk < 64; kk++) {
            float a[4], bb[4];
            *(float4*)&a[0]  = *(const float4*)&Qt[kk*FA_TP + ty*4];
            *(float4*)&bb[0] = *(const float4*)&Kt[kk*FA_TP + tx*4];
            #pragma unroll
            for (int i = 0; i < 4; i++)
                #pragma unroll
                for (int j = 0; j < 4; j++)
                    s[i][j] = fmaf(a[i], bb[j], s[i][j]);
        }

        const bool diag = (kt == qt);
        #pragma unroll
        for (int i = 0; i < 4; i++)
            #pragma unroll
            for (int j = 0; j < 4; j++) {
                float v = s[i][j] * scale;
                if (diag && (tx*4 + j) > (ty*4 + i)) v = -INFINITY;
                S[(ty*4+i)*FA_TP + tx*4+j] = v;
            }
        __syncthreads();

        if (tid < 64) {
            const int r = tid;
            float* Sr = S + r*FA_TP;
            float vmax = -INFINITY;
            for (int c = 0; c < 64; c++) {
                int cc = (c + r) & 63;
                vmax = fmaxf(vmax, Sr[cc]);
            }
            float mold = mS[r];
            float mnew = fmaxf(mold, vmax);
            float sum = 0.f;
            for (int c = 0; c < 64; c++) {
                int cc = (c + r) & 63;
                float e2 = expf(Sr[cc] - mnew);
                Sr[cc] = e2;
                sum += e2;
            }
            float al = expf(mold - mnew);
            aS[r] = al;
            lS[r] = lS[r] * al + sum;
            mS[r] = mnew;
        }
        __syncthreads();

        float alr[4];
        #pragma unroll
        for (int i = 0; i < 4; i++) alr[i] = aS[ty*4+i];
        #pragma unroll
        for (int i = 0; i < 4; i++)
            #pragma unroll
            for (int j = 0; j < 4; j++) o[i][j] *= alr[i];

        #pragma unroll 8
        for (int c = 0; c < 64; c++) {
            float vv[4];
            *(float4*)&vv[0] = *(const float4*)&Vs[c*FA_TP + tx*4];
            float pr[4];
            #pragma unroll
            for (int i = 0; i < 4; i++) pr[i] = S[(ty*4+i)*FA_TP + c];
            #pragma unroll
            for (int i = 0; i < 4; i++)
                #pragma unroll
                for (int j = 0; j < 4; j++)
                    o[i][j] = fmaf(pr[i], vv[j], o[i][j]);
        }
        __syncthreads();
    }

    #pragma unroll
    for (int i = 0; i < 4; i++) {
        float inv = 1.f / lS[ty*4+i];
        #pragma unroll
        for (int j = 0; j < 4; j++)
            O[((size_t)(b*SEQ) + qt*64 + ty*4 + i) * D_MODEL + h*HD + tx*4 + j]
                = o[i][j] * inv;
    }
}

// ---------------------------------------------------------------------------
extern "C" void kernel_launch(void* const* d_in, const int* in_sizes, int n_in,
                              void* d_out, int out_size)
{
    (void)in_sizes; (void)n_in; (void)out_size;
    const float* x  = (const float*)d_in[0];
    const float* wq = (const float*)d_in[1];
    const float* wk = (const float*)d_in[2];
    const float* wv = (const float*)d_in[3];
    const float* wo = (const float*)d_in[4];
    float* out = (float*)d_out;

    float *q, *k, *v, *attn;
    cudaGetSymbolAddress((void**)&q,    g_q);
    cudaGetSymbolAddress((void**)&k,    g_k);
    cudaGetSymbolAddress((void**)&v,    g_v);
    cudaGetSymbolAddress((void**)&attn, g_attn);

    cudaFuncSetAttribute(flash_attn, cudaFuncAttributeMaxDynamicSharedMemorySize,
                         FA_SMEM);

    dim3 blk(256);
    // projections
    sgemm_abt<<<dim3(D_MODEL/128, MROWS/128), blk>>>(x, wq, q, D_MODEL, D_MODEL);
    sgemm_abt<<<dim3(KVW/128,    MROWS/128), blk>>>(x, wk, k, KVW,     D_MODEL);
    sgemm_abt<<<dim3(KVW/128,    MROWS/128), blk>>>(x, wv, v, KVW,     D_MODEL);
    // sign-flipped interleaved rope
    rope_kernel<<<(MROWS*(D_MODEL/2) + 255)/256, 256>>>(q, D_MODEL);
    rope_kernel<<<(MROWS*(KVW/2)    + 255)/256, 256>>>(k, KVW);
    // attention
    flash_attn<<<dim3(SEQ/64, NH, NBATCH), blk, FA_SMEM>>>(q, k, v, attn);
    // output projection
    sgemm_abt<<<dim3(D_MODEL/128, MROWS/128), blk>>>(attn, wo, out, D_MODEL, D_MODEL);
}

// round 9
// speedup vs baseline: 1.6154x; 1.6154x over previous
#include <cuda_runtime.h>
#include <math.h>
#include <stdint.h>

#define D_MODEL 2048
#define SEQ     2048
#define NBATCH  2
#define NH      32
#define NKV     8
#define HD      64
#define NREP    4
#define KVW     (NKV*HD)        // 512
#define MROWS   (NBATCH*SEQ)    // 4096

// scratch (static device globals — no allocations allowed)
__device__ float g_q[(size_t)MROWS * D_MODEL];
__device__ float g_k[(size_t)MROWS * KVW];
__device__ float g_v[(size_t)MROWS * KVW];
__device__ float g_attn[(size_t)MROWS * D_MODEL];

__device__ __forceinline__ uint32_t f2tf32(float x) {
    uint32_t r;
    asm("cvt.rna.tf32.f32 %0, %1;" : "=r"(r) : "f"(x));
    return r;
}

// ---------------------------------------------------------------------------
// TF32 tensor-core GEMM: C[M,N] = A[M,K] @ B[N,K]^T  (row-major all)
// 128x128x16 block tile, 256 threads = 8 warps (2m x 4n), warp = 64x32.
// mma.m16n8k8: warp does 4 m-tiles x 4 n-tiles per 8-k step.
// smem k-major [16][136] with xor-16 swizzle: conflict-free LDS and STS.
// ---------------------------------------------------------------------------
__global__ __launch_bounds__(256)
void gemm_tf32(const float* __restrict__ A, const float* __restrict__ B,
               float* __restrict__ C, int N, int K)
{
    __shared__ uint32_t As[16][136];
    __shared__ uint32_t Bs[16][136];

    const int tid  = threadIdx.x;
    const int lane = tid & 31;
    const int warp = tid >> 5;
    const int wm = (warp & 1) * 64;     // warp m offset
    const int wn = (warp >> 1) * 32;    // warp n offset
    const int lr = lane >> 2;           // 0..7
    const int lc = lane & 3;            // 0..3

    const float* Ab = A + (size_t)blockIdx.y * 128 * K;
    const float* Bb = B + (size_t)blockIdx.x * 128 * K;

    float c[4][4][4];
    #pragma unroll
    for (int mt = 0; mt < 4; mt++)
        #pragma unroll
        for (int nt = 0; nt < 4; nt++)
            #pragma unroll
            for (int e = 0; e < 4; e++) c[mt][nt][e] = 0.f;

    const int row = tid >> 1;           // 0..127
    const int kq  = (tid & 1) * 8;      // 0 or 8
    const int rs  = row ^ ((kq >> 3) << 4);   // xor-swizzled store column

    for (int k0 = 0; k0 < K; k0 += 16) {
        float4 av0 = *(const float4*)(Ab + (size_t)row * K + k0 + kq);
        float4 av1 = *(const float4*)(Ab + (size_t)row * K + k0 + kq + 4);
        float4 bv0 = *(const float4*)(Bb + (size_t)row * K + k0 + kq);
        float4 bv1 = *(const float4*)(Bb + (size_t)row * K + k0 + kq + 4);
        As[kq+0][rs] = f2tf32(av0.x); As[kq+1][rs] = f2tf32(av0.y);
        As[kq+2][rs] = f2tf32(av0.z); As[kq+3][rs] = f2tf32(av0.w);
        As[kq+4][rs] = f2tf32(av1.x); As[kq+5][rs] = f2tf32(av1.y);
        As[kq+6][rs] = f2tf32(av1.z); As[kq+7][rs] = f2tf32(av1.w);
        Bs[kq+0][rs] = f2tf32(bv0.x); Bs[kq+1][rs] = f2tf32(bv0.y);
        Bs[kq+2][rs] = f2tf32(bv0.z); Bs[kq+3][rs] = f2tf32(bv0.w);
        Bs[kq+4][rs] = f2tf32(bv1.x); Bs[kq+5][rs] = f2tf32(bv1.y);
        Bs[kq+6][rs] = f2tf32(bv1.z); Bs[kq+7][rs] = f2tf32(bv1.w);
        __syncthreads();

        #pragma unroll
        for (int ks = 0; ks < 2; ks++) {
            const int kb = ks * 8;
            const int xr = ks << 4;
            uint32_t af[4][4], bf[4][2];
            #pragma unroll
            for (int mt = 0; mt < 4; mt++) {
                int r0 = wm + mt * 16 + lr;
                af[mt][0] = As[kb+lc  ][(r0    ) ^ xr];
                af[mt][1] = As[kb+lc  ][(r0 + 8) ^ xr];
                af[mt][2] = As[kb+lc+4][(r0    ) ^ xr];
                af[mt][3] = As[kb+lc+4][(r0 + 8) ^ xr];
            }
            #pragma unroll
            for (int nt = 0; nt < 4; nt++) {
                int n0 = wn + nt * 8 + lr;
                bf[nt][0] = Bs[kb+lc  ][n0 ^ xr];
                bf[nt][1] = Bs[kb+lc+4][n0 ^ xr];
            }
            #pragma unroll
            for (int mt = 0; mt < 4; mt++)
                #pragma unroll
                for (int nt = 0; nt < 4; nt++)
                    asm volatile(
                        "mma.sync.aligned.m16n8k8.row.col.f32.tf32.tf32.f32 "
                        "{%0,%1,%2,%3}, {%4,%5,%6,%7}, {%8,%9}, {%0,%1,%2,%3};"
                        : "+f"(c[mt][nt][0]), "+f"(c[mt][nt][1]),
                          "+f"(c[mt][nt][2]), "+f"(c[mt][nt][3])
                        : "r"(af[mt][0]), "r"(af[mt][1]),
                          "r"(af[mt][2]), "r"(af[mt][3]),
                          "r"(bf[nt][0]), "r"(bf[nt][1]));
        }
        __syncthreads();
    }

    #pragma unroll
    for (int mt = 0; mt < 4; mt++) {
        int r0 = blockIdx.y * 128 + wm + mt * 16 + lr;
        #pragma unroll
        for (int nt = 0; nt < 4; nt++) {
            int cc = blockIdx.x * 128 + wn + nt * 8 + lc * 2;
            *(float2*)(C + (size_t)r0 * N + cc) =
                make_float2(c[mt][nt][0], c[mt][nt][1]);
            *(float2*)(C + (size_t)(r0 + 8) * N + cc) =
                make_float2(c[mt][nt][2], c[mt][nt][3]);
        }
    }
}

// ---------------------------------------------------------------------------
// SIGN-FLIPPED interleaved RoPE (rotation by -theta), in-place.  [VERIFIED]
// ---------------------------------------------------------------------------
__global__ void rope_kernel(float* __restrict__ buf, int width)
{
    int idx = blockIdx.x * blockDim.x + threadIdx.x;
    int ppr = width >> 1;
    if (idx >= MROWS * ppr) return;
    int m = idx / ppr;
    int p = idx - m * ppr;
    int i = p & 31;
    int s = m & (SEQ - 1);
    float inv = powf(10000.0f, -((float)(2*i)) / 64.0f);
    float ang = (float)s * inv;
    float c, sn;
    sincosf(ang, &c, &sn);
    sn = -sn;                              // rotation by -theta (reference conv.)
    float* el = buf + (size_t)m * width + 2*p;
    float xr = el[0], xi = el[1];
    el[0] = xr * c - xi * sn;
    el[1] = xr * sn + xi * c;
}

// ---------------------------------------------------------------------------
// Flash attention, causal, GQA.  BM=BN=64, 256 threads (16x16, 4x4/thread).
// Register online-softmax + shfl reductions (verified function-equal).
// smem: Qt[64][68], KP[64][68] (K then P), Vs[64][64]
// ---------------------------------------------------------------------------
#define FLASH_SMEM ((64*68 + 64*68 + 64*64) * 4)

__global__ __launch_bounds__(256)
void flash_attn(const float* __restrict__ Q, const float* __restrict__ K,
                const float* __restrict__ V, float* __restrict__ O)
{
    extern __shared__ float sm[];
    float* Qt = sm;               // [64][68]  Qt[d][r]
    float* KP = sm + 64*68;       // [64][68]  Kt[d][c]  /  P[r][c]
    float* Vs = KP + 64*68;       // [64][64]  Vs[c][d]

    const int qt = blockIdx.x, h = blockIdx.y, b = blockIdx.z;
    const int kh = h >> 2;        // NREP = 4
    const int tid = threadIdx.x;
    const int tx = tid & 15, ty = tid >> 4;
    const float scale = 0.125f;   // 64^-0.5

    for (int e = tid; e < 64*64; e += 256) {
        int r = e >> 6, d = e & 63;
        Qt[d*68 + r] = Q[((size_t)(b*SEQ) + qt*64 + r) * D_MODEL + h*HD + d];
    }

    float o[4][4];
    float mrow[4], lrow[4];
    #pragma unroll
    for (int i = 0; i < 4; i++) {
        mrow[i] = -INFINITY; lrow[i] = 0.f;
        #pragma unroll
        for (int j = 0; j < 4; j++) o[i][j] = 0.f;
    }

    for (int kt = 0; kt <= qt; kt++) {
        for (int e = tid; e < 64*64; e += 256) {
            int c = e >> 6, d = e & 63;
            size_t gi = ((size_t)(b*SEQ) + kt*64 + c) * KVW + kh*HD + d;
            KP[d*68 + c] = K[gi];
            Vs[c*64 + d] = V[gi];
        }
        __syncthreads();

        float s[4][4];
        #pragma unroll
        for (int i = 0; i < 4; i++)
            #pragma unroll
            for (int j = 0; j < 4; j++) s[i][j] = 0.f;

        #pragma unroll 8
        for (int kk = 0; kk < 64; kk++) {
            float a[4], bb[4];
            *(float4*)&a[0]  = *(const float4*)&Qt[kk*68 + ty*4];
            *(float4*)&bb[0] = *(const float4*)&KP[kk*68 + tx*4];
            #pragma unroll
            for (int i = 0; i < 4; i++)
                #pragma unroll
                for (int j = 0; j < 4; j++)
                    s[i][j] = fmaf(a[i], bb[j], s[i][j]);
        }

        const bool diag = (kt == qt);
        #pragma unroll
        for (int i = 0; i < 4; i++)
            #pragma unroll
            for (int j = 0; j < 4; j++) {
                float v = s[i][j] * scale;
                if (diag && (tx*4 + j) > (ty*4 + i)) v = -INFINITY;
                s[i][j] = v;
            }

        float alpha[4];
        #pragma unroll
        for (int i = 0; i < 4; i++) {
            float vmax = fmaxf(fmaxf(s[i][0], s[i][1]), fmaxf(s[i][2], s[i][3]));
            #pragma unroll
            for (int off = 1; off < 16; off <<= 1)
                vmax = fmaxf(vmax, __shfl_xor_sync(0xffffffffu, vmax, off));
            float mnew = fmaxf(mrow[i], vmax);
            float rs = 0.f;
            #pragma unroll
            for (int j = 0; j < 4; j++) {
                s[i][j] = __expf(s[i][j] - mnew);
                rs += s[i][j];
            }
            #pragma unroll
            for (int off = 1; off < 16; off <<= 1)
                rs += __shfl_xor_sync(0xffffffffu, rs, off);
            alpha[i] = __expf(mrow[i] - mnew);
            lrow[i] = lrow[i] * alpha[i] + rs;
            mrow[i] = mnew;
        }
        #pragma unroll
        for (int i = 0; i < 4; i++)
            #pragma unroll
            for (int j = 0; j < 4; j++) o[i][j] *= alpha[i];

        __syncthreads();   // done reading K before overwriting with P

        #pragma unroll
        for (int i = 0; i < 4; i++)
            #pragma unroll
            for (int j = 0; j < 4; j++)
                KP[(ty*4+i)*68 + tx*4+j] = s[i][j];
        __syncthreads();

        #pragma unroll 8
        for (int c = 0; c < 64; c++) {
            float vv[4];
            *(float4*)&vv[0] = *(const float4*)&Vs[c*64 + tx*4];
            float pr[4];
            #pragma unroll
            for (int i = 0; i < 4; i++) pr[i] = KP[(ty*4+i)*68 + c];
            #pragma unroll
            for (int i = 0; i < 4; i++)
                #pragma unroll
                for (int j = 0; j < 4; j++)
                    o[i][j] = fmaf(pr[i], vv[j], o[i][j]);
        }
        __syncthreads();
    }

    #pragma unroll
    for (int i = 0; i < 4; i++) {
        float inv = 1.f / lrow[i];
        #pragma unroll
        for (int j = 0; j < 4; j++)
            O[((size_t)(b*SEQ) + qt*64 + ty*4 + i) * D_MODEL + h*HD + tx*4 + j]
                = o[i][j] * inv;
    }
}

// ---------------------------------------------------------------------------
extern "C" void kernel_launch(void* const* d_in, const int* in_sizes, int n_in,
                              void* d_out, int out_size)
{
    (void)in_sizes; (void)n_in; (void)out_size;
    const float* x  = (const float*)d_in[0];
    const float* wq = (const float*)d_in[1];
    const float* wk = (const float*)d_in[2];
    const float* wv = (const float*)d_in[3];
    const float* wo = (const float*)d_in[4];
    float* out = (float*)d_out;

    float *q, *k, *v, *attn;
    cudaGetSymbolAddress((void**)&q,    g_q);
    cudaGetSymbolAddress((void**)&k,    g_k);
    cudaGetSymbolAddress((void**)&v,    g_v);
    cudaGetSymbolAddress((void**)&attn, g_attn);

    cudaFuncSetAttribute(flash_attn, cudaFuncAttributeMaxDynamicSharedMemorySize,
                         FLASH_SMEM);

    // projections (tf32 tensor cores)
    gemm_tf32<<<dim3(D_MODEL/128, MROWS/128), 256>>>(x, wq, q, D_MODEL, D_MODEL);
    gemm_tf32<<<dim3(KVW/128,    MROWS/128), 256>>>(x, wk, k, KVW,     D_MODEL);
    gemm_tf32<<<dim3(KVW/128,    MROWS/128), 256>>>(x, wv, v, KVW,     D_MODEL);
    // sign-flipped interleaved rope
    rope_kernel<<<(MROWS*(D_MODEL/2) + 255)/256, 256>>>(q, D_MODEL);
    rope_kernel<<<(MROWS*(KVW/2)    + 255)/256, 256>>>(k, KVW);
    // attention (fp32, verified)
    flash_attn<<<dim3(SEQ/64, NH, NBATCH), 256, FLASH_SMEM>>>(q, k, v, attn);
    // output projection
    gemm_tf32<<<dim3(D_MODEL/128, MROWS/128), 256>>>(attn, wo, out, D_MODEL, D_MODEL);
}

// round 10
// speedup vs baseline: 1.6597x; 1.0274x over previous
#include <cuda_runtime.h>
#include <math.h>
#include <stdint.h>

#define D_MODEL 2048
#define SEQ     2048
#define NBATCH  2
#define NH      32
#define NKV     8
#define HD      64
#define NREP    4
#define KVW     (NKV*HD)        // 512
#define MROWS   (NBATCH*SEQ)    // 4096

// scratch (static device globals — no allocations allowed)
__device__ float g_q[(size_t)MROWS * D_MODEL];
__device__ float g_k[(size_t)MROWS * KVW];
__device__ float g_v[(size_t)MROWS * KVW];
__device__ float g_attn[(size_t)MROWS * D_MODEL];

__device__ __forceinline__ uint32_t f2tf32(float x) {
    uint32_t r;
    asm("cvt.rna.tf32.f32 %0, %1;" : "=r"(r) : "f"(x));
    return r;
}

// ---------------------------------------------------------------------------
// TF32 tensor-core GEMM: C[M,N] = A[M,K] @ B[N,K]^T  (row-major all)
// 128x128x16 block tile, 256 threads = 8 warps (2m x 4n), warp = 64x32.
// mma.m16n8k8: warp does 4 m-tiles x 4 n-tiles per 8-k step.
// smem k-major [16][136] with xor-16 swizzle: conflict-free LDS and STS.
// ---------------------------------------------------------------------------
__global__ __launch_bounds__(256)
void gemm_tf32(const float* __restrict__ A, const float* __restrict__ B,
               float* __restrict__ C, int N, int K)
{
    __shared__ uint32_t As[16][136];
    __shared__ uint32_t Bs[16][136];

    const int tid  = threadIdx.x;
    const int lane = tid & 31;
    const int warp = tid >> 5;
    const int wm = (warp & 1) * 64;     // warp m offset
    const int wn = (warp >> 1) * 32;    // warp n offset
    const int lr = lane >> 2;           // 0..7
    const int lc = lane & 3;            // 0..3

    const float* Ab = A + (size_t)blockIdx.y * 128 * K;
    const float* Bb = B + (size_t)blockIdx.x * 128 * K;

    float c[4][4][4];
    #pragma unroll
    for (int mt = 0; mt < 4; mt++)
        #pragma unroll
        for (int nt = 0; nt < 4; nt++)
            #pragma unroll
            for (int e = 0; e < 4; e++) c[mt][nt][e] = 0.f;

    const int row = tid >> 1;           // 0..127
    const int kq  = (tid & 1) * 8;      // 0 or 8
    const int rs  = row ^ ((kq >> 3) << 4);   // xor-swizzled store column

    for (int k0 = 0; k0 < K; k0 += 16) {
        float4 av0 = *(const float4*)(Ab + (size_t)row * K + k0 + kq);
        float4 av1 = *(const float4*)(Ab + (size_t)row * K + k0 + kq + 4);
        float4 bv0 = *(const float4*)(Bb + (size_t)row * K + k0 + kq);
        float4 bv1 = *(const float4*)(Bb + (size_t)row * K + k0 + kq + 4);
        As[kq+0][rs] = f2tf32(av0.x); As[kq+1][rs] = f2tf32(av0.y);
        As[kq+2][rs] = f2tf32(av0.z); As[kq+3][rs] = f2tf32(av0.w);
        As[kq+4][rs] = f2tf32(av1.x); As[kq+5][rs] = f2tf32(av1.y);
        As[kq+6][rs] = f2tf32(av1.z); As[kq+7][rs] = f2tf32(av1.w);
        Bs[kq+0][rs] = f2tf32(bv0.x); Bs[kq+1][rs] = f2tf32(bv0.y);
        Bs[kq+2][rs] = f2tf32(bv0.z); Bs[kq+3][rs] = f2tf32(bv0.w);
        Bs[kq+4][rs] = f2tf32(bv1.x); Bs[kq+5][rs] = f2tf32(bv1.y);
        Bs[kq+6][rs] = f2tf32(bv1.z); Bs[kq+7][rs] = f2tf32(bv1.w);
        __syncthreads();

        #pragma unroll
        for (int ks = 0; ks < 2; ks++) {
            const int kb = ks * 8;
            const int xr = ks << 4;
            uint32_t af[4][4], bf[4][2];
            #pragma unroll
            for (int mt = 0; mt < 4; mt++) {
                int r0 = wm + mt * 16 + lr;
                af[mt][0] = As[kb+lc  ][(r0    ) ^ xr];
                af[mt][1] = As[kb+lc  ][(r0 + 8) ^ xr];
                af[mt][2] = As[kb+lc+4][(r0    ) ^ xr];
                af[mt][3] = As[kb+lc+4][(r0 + 8) ^ xr];
            }
            #pragma unroll
            for (int nt = 0; nt < 4; nt++) {
                int n0 = wn + nt * 8 + lr;
                bf[nt][0] = Bs[kb+lc  ][n0 ^ xr];
                bf[nt][1] = Bs[kb+lc+4][n0 ^ xr];
            }
            #pragma unroll
            for (int mt = 0; mt < 4; mt++)
                #pragma unroll
                for (int nt = 0; nt < 4; nt++)
                    asm volatile(
                        "mma.sync.aligned.m16n8k8.row.col.f32.tf32.tf32.f32 "
                        "{%0,%1,%2,%3}, {%4,%5,%6,%7}, {%8,%9}, {%0,%1,%2,%3};"
                        : "+f"(c[mt][nt][0]), "+f"(c[mt][nt][1]),
                          "+f"(c[mt][nt][2]), "+f"(c[mt][nt][3])
                        : "r"(af[mt][0]), "r"(af[mt][1]),
                          "r"(af[mt][2]), "r"(af[mt][3]),
                          "r"(bf[nt][0]), "r"(bf[nt][1]));
        }
        __syncthreads();
    }

    #pragma unroll
    for (int mt = 0; mt < 4; mt++) {
        int r0 = blockIdx.y * 128 + wm + mt * 16 + lr;
        #pragma unroll
        for (int nt = 0; nt < 4; nt++) {
            int cc = blockIdx.x * 128 + wn + nt * 8 + lc * 2;
            *(float2*)(C + (size_t)r0 * N + cc) =
                make_float2(c[mt][nt][0], c[mt][nt][1]);
            *(float2*)(C + (size_t)(r0 + 8) * N + cc) =
                make_float2(c[mt][nt][2], c[mt][nt][3]);
        }
    }
}

// ---------------------------------------------------------------------------
// SIGN-FLIPPED interleaved RoPE (rotation by -theta), in-place.  [VERIFIED]
// ---------------------------------------------------------------------------
__global__ void rope_kernel(float* __restrict__ buf, int width)
{
    int idx = blockIdx.x * blockDim.x + threadIdx.x;
    int ppr = width >> 1;
    if (idx >= MROWS * ppr) return;
    int m = idx / ppr;
    int p = idx - m * ppr;
    int i = p & 31;
    int s = m & (SEQ - 1);
    float inv = powf(10000.0f, -((float)(2*i)) / 64.0f);
    float ang = (float)s * inv;
    float c, sn;
    sincosf(ang, &c, &sn);
    sn = -sn;                              // rotation by -theta (reference conv.)
    float* el = buf + (size_t)m * width + 2*p;
    float xr = el[0], xi = el[1];
    el[0] = xr * c - xi * sn;
    el[1] = xr * sn + xi * c;
}

// ---------------------------------------------------------------------------
// Flash attention, causal, GQA.  BM=BN=64, 256 threads (16x16, 4x4/thread).
// Register online-softmax + shfl reductions (verified function-equal).
// smem: Qt[64][68], KP[64][68] (K then P), Vs[64][64]
// ---------------------------------------------------------------------------
#define FLASH_SMEM ((64*68 + 64*68 + 64*64) * 4)

__global__ __launch_bounds__(256)
void flash_attn(const float* __restrict__ Q, const float* __restrict__ K,
                const float* __restrict__ V, float* __restrict__ O)
{
    extern __shared__ float sm[];
    float* Qt = sm;               // [64][68]  Qt[d][r]
    float* KP = sm + 64*68;       // [64][68]  Kt[d][c]  /  P[r][c]
    float* Vs = KP + 64*68;       // [64][64]  Vs[c][d]

    const int qt = blockIdx.x, h = blockIdx.y, b = blockIdx.z;
    const int kh = h >> 2;        // NREP = 4
    const int tid = threadIdx.x;
    const int tx = tid & 15, ty = tid >> 4;
    const float scale = 0.125f;   // 64^-0.5

    for (int e = tid; e < 64*64; e += 256) {
        int r = e >> 6, d = e & 63;
        Qt[d*68 + r] = Q[((size_t)(b*SEQ) + qt*64 + r) * D_MODEL + h*HD + d];
    }

    float o[4][4];
    float mrow[4], lrow[4];
    #pragma unroll
    for (int i = 0; i < 4; i++) {
        mrow[i] = -INFINITY; lrow[i] = 0.f;
        #pragma unroll
        for (int j = 0; j < 4; j++) o[i][j] = 0.f;
    }

    for (int kt = 0; kt <= qt; kt++) {
        for (int e = tid; e < 64*64; e += 256) {
            int c = e >> 6, d = e & 63;
            size_t gi = ((size_t)(b*SEQ) + kt*64 + c) * KVW + kh*HD + d;
            KP[d*68 + c] = K[gi];
            Vs[c*64 + d] = V[gi];
        }
        __syncthreads();

        float s[4][4];
        #pragma unroll
        for (int i = 0; i < 4; i++)
            #pragma unroll
            for (int j = 0; j < 4; j++) s[i][j] = 0.f;

        #pragma unroll 8
        for (int kk = 0; kk < 64; kk++) {
            float a[4], bb[4];
            *(float4*)&a[0]  = *(const float4*)&Qt[kk*68 + ty*4];
            *(float4*)&bb[0] = *(const float4*)&KP[kk*68 + tx*4];
            #pragma unroll
            for (int i = 0; i < 4; i++)
                #pragma unroll
                for (int j = 0; j < 4; j++)
                    s[i][j] = fmaf(a[i], bb[j], s[i][j]);
        }

        const bool diag = (kt == qt);
        #pragma unroll
        for (int i = 0; i < 4; i++)
            #pragma unroll
            for (int j = 0; j < 4; j++) {
                float v = s[i][j] * scale;
                if (diag && (tx*4 + j) > (ty*4 + i)) v = -INFINITY;
                s[i][j] = v;
            }

        float alpha[4];
        #pragma unroll
        for (int i = 0; i < 4; i++) {
            float vmax = fmaxf(fmaxf(s[i][0], s[i][1]), fmaxf(s[i][2], s[i][3]));
            #pragma unroll
            for (int off = 1; off < 16; off <<= 1)
                vmax = fmaxf(vmax, __shfl_xor_sync(0xffffffffu, vmax, off));
            float mnew = fmaxf(mrow[i], vmax);
            float rs = 0.f;
            #pragma unroll
            for (int j = 0; j < 4; j++) {
                s[i][j] = __expf(s[i][j] - mnew);
                rs += s[i][j];
            }
            #pragma unroll
            for (int off = 1; off < 16; off <<= 1)
                rs += __shfl_xor_sync(0xffffffffu, rs, off);
            alpha[i] = __expf(mrow[i] - mnew);
            lrow[i] = lrow[i] * alpha[i] + rs;
            mrow[i] = mnew;
        }
        #pragma unroll
        for (int i = 0; i < 4; i++)
            #pragma unroll
            for (int j = 0; j < 4; j++) o[i][j] *= alpha[i];

        __syncthreads();   // done reading K before overwriting with P

        #pragma unroll
        for (int i = 0; i < 4; i++)
            #pragma unroll
            for (int j = 0; j < 4; j++)
                KP[(ty*4+i)*68 + tx*4+j] = s[i][j];
        __syncthreads();

        #pragma unroll 8
        for (int c = 0; c < 64; c++) {
            float vv[4];
            *(float4*)&vv[0] = *(const float4*)&Vs[c*64 + tx*4];
            float pr[4];
            #pragma unroll
            for (int i = 0; i < 4; i++) pr[i] = KP[(ty*4+i)*68 + c];
            #pragma unroll
            for (int i = 0; i < 4; i++)
                #pragma unroll
                for (int j = 0; j < 4; j++)
                    o[i][j] = fmaf(pr[i], vv[j], o[i][j]);
        }
        __syncthreads();
    }

    #pragma unroll
    for (int i = 0; i < 4; i++) {
        float inv = 1.f / lrow[i];
        #pragma unroll
        for (int j = 0; j < 4; j++)
            O[((size_t)(b*SEQ) + qt*64 + ty*4 + i) * D_MODEL + h*HD + tx*4 + j]
                = o[i][j] * inv;
    }
}

// ---------------------------------------------------------------------------
extern "C" void kernel_launch(void* const* d_in, const int* in_sizes, int n_in,
                              void* d_out, int out_size)
{
    (void)in_sizes; (void)n_in; (void)out_size;
    const float* x  = (const float*)d_in[0];
    const float* wq = (const float*)d_in[1];
    const float* wk = (const float*)d_in[2];
    const float* wv = (const float*)d_in[3];
    const float* wo = (const float*)d_in[4];
    float* out = (float*)d_out;

    float *q, *k, *v, *attn;
    cudaGetSymbolAddress((void**)&q,    g_q);
    cudaGetSymbolAddress((void**)&k,    g_k);
    cudaGetSymbolAddress((void**)&v,    g_v);
    cudaGetSymbolAddress((void**)&attn, g_attn);

    cudaFuncSetAttribute(flash_attn, cudaFuncAttributeMaxDynamicSharedMemorySize,
                         FLASH_SMEM);

    // projections (tf32 tensor cores)
    gemm_tf32<<<dim3(D_MODEL/128, MROWS/128), 256>>>(x, wq, q, D_MODEL, D_MODEL);
    gemm_tf32<<<dim3(KVW/128,    MROWS/128), 256>>>(x, wk, k, KVW,     D_MODEL);
    gemm_tf32<<<dim3(KVW/128,    MROWS/128), 256>>>(x, wv, v, KVW,     D_MODEL);
    // sign-flipped interleaved rope
    rope_kernel<<<(MROWS*(D_MODEL/2) + 255)/256, 256>>>(q, D_MODEL);
    rope_kernel<<<(MROWS*(KVW/2)    + 255)/256, 256>>>(k, KVW);
    // attention (fp32, verified)
    flash_attn<<<dim3(SEQ/64, NH, NBATCH), 256, FLASH_SMEM>>>(q, k, v, attn);
    // output projection
    gemm_tf32<<<dim3(D_MODEL/128, MROWS/128), 256>>>(attn, wo, out, D_MODEL, D_MODEL);
}

// round 11
// speedup vs baseline: 2.5234x; 1.5204x over previous
#include <cuda_runtime.h>
#include <math.h>
#include <stdint.h>

#define D_MODEL 2048
#define SEQ     2048
#define NBATCH  2
#define NH      32
#define NKV     8
#define HD      64
#define NREP    4
#define KVW     (NKV*HD)        // 512
#define MROWS   (NBATCH*SEQ)    // 4096

// scratch (static device globals — no allocations allowed)
__device__ float g_q[(size_t)MROWS * D_MODEL];
__device__ float g_k[(size_t)MROWS * KVW];
__device__ float g_v[(size_t)MROWS * KVW];
__device__ float g_attn[(size_t)MROWS * D_MODEL];

__device__ __forceinline__ uint32_t f2tf32(float x) {
    uint32_t r;
    asm("cvt.rna.tf32.f32 %0, %1;" : "=r"(r) : "f"(x));
    return r;
}

#define MMA_TF32(C, A, B)                                                     \
    asm volatile(                                                             \
        "mma.sync.aligned.m16n8k8.row.col.f32.tf32.tf32.f32 "                \
        "{%0,%1,%2,%3}, {%4,%5,%6,%7}, {%8,%9}, {%0,%1,%2,%3};"              \
        : "+f"((C)[0]), "+f"((C)[1]), "+f"((C)[2]), "+f"((C)[3])             \
        : "r"((A)[0]), "r"((A)[1]), "r"((A)[2]), "r"((A)[3]),                \
          "r"((B)[0]), "r"((B)[1]))

// ---------------------------------------------------------------------------
// TF32 tensor-core GEMM: C[M,N] = A[M,K] @ B[N,K]^T  (row-major all)  [R9]
// ---------------------------------------------------------------------------
__global__ __launch_bounds__(256)
void gemm_tf32(const float* __restrict__ A, const float* __restrict__ B,
               float* __restrict__ C, int N, int K)
{
    __shared__ uint32_t As[16][136];
    __shared__ uint32_t Bs[16][136];

    const int tid  = threadIdx.x;
    const int lane = tid & 31;
    const int warp = tid >> 5;
    const int wm = (warp & 1) * 64;
    const int wn = (warp >> 1) * 32;
    const int lr = lane >> 2;
    const int lc = lane & 3;

    const float* Ab = A + (size_t)blockIdx.y * 128 * K;
    const float* Bb = B + (size_t)blockIdx.x * 128 * K;

    float c[4][4][4];
    #pragma unroll
    for (int mt = 0; mt < 4; mt++)
        #pragma unroll
        for (int nt = 0; nt < 4; nt++)
            #pragma unroll
            for (int e = 0; e < 4; e++) c[mt][nt][e] = 0.f;

    const int row = tid >> 1;
    const int kq  = (tid & 1) * 8;
    const int rs  = row ^ ((kq >> 3) << 4);

    for (int k0 = 0; k0 < K; k0 += 16) {
        float4 av0 = *(const float4*)(Ab + (size_t)row * K + k0 + kq);
        float4 av1 = *(const float4*)(Ab + (size_t)row * K + k0 + kq + 4);
        float4 bv0 = *(const float4*)(Bb + (size_t)row * K + k0 + kq);
        float4 bv1 = *(const float4*)(Bb + (size_t)row * K + k0 + kq + 4);
        As[kq+0][rs] = f2tf32(av0.x); As[kq+1][rs] = f2tf32(av0.y);
        As[kq+2][rs] = f2tf32(av0.z); As[kq+3][rs] = f2tf32(av0.w);
        As[kq+4][rs] = f2tf32(av1.x); As[kq+5][rs] = f2tf32(av1.y);
        As[kq+6][rs] = f2tf32(av1.z); As[kq+7][rs] = f2tf32(av1.w);
        Bs[kq+0][rs] = f2tf32(bv0.x); Bs[kq+1][rs] = f2tf32(bv0.y);
        Bs[kq+2][rs] = f2tf32(bv0.z); Bs[kq+3][rs] = f2tf32(bv0.w);
        Bs[kq+4][rs] = f2tf32(bv1.x); Bs[kq+5][rs] = f2tf32(bv1.y);
        Bs[kq+6][rs] = f2tf32(bv1.z); Bs[kq+7][rs] = f2tf32(bv1.w);
        __syncthreads();

        #pragma unroll
        for (int ks = 0; ks < 2; ks++) {
            const int kb = ks * 8;
            const int xr = ks << 4;
            uint32_t af[4][4], bf[4][2];
            #pragma unroll
            for (int mt = 0; mt < 4; mt++) {
                int r0 = wm + mt * 16 + lr;
                af[mt][0] = As[kb+lc  ][(r0    ) ^ xr];
                af[mt][1] = As[kb+lc  ][(r0 + 8) ^ xr];
                af[mt][2] = As[kb+lc+4][(r0    ) ^ xr];
                af[mt][3] = As[kb+lc+4][(r0 + 8) ^ xr];
            }
            #pragma unroll
            for (int nt = 0; nt < 4; nt++) {
                int n0 = wn + nt * 8 + lr;
                bf[nt][0] = Bs[kb+lc  ][n0 ^ xr];
                bf[nt][1] = Bs[kb+lc+4][n0 ^ xr];
            }
            #pragma unroll
            for (int mt = 0; mt < 4; mt++)
                #pragma unroll
                for (int nt = 0; nt < 4; nt++)
                    MMA_TF32(c[mt][nt], af[mt], bf[nt]);
        }
        __syncthreads();
    }

    #pragma unroll
    for (int mt = 0; mt < 4; mt++) {
        int r0 = blockIdx.y * 128 + wm + mt * 16 + lr;
        #pragma unroll
        for (int nt = 0; nt < 4; nt++) {
            int cc = blockIdx.x * 128 + wn + nt * 8 + lc * 2;
            *(float2*)(C + (size_t)r0 * N + cc) =
                make_float2(c[mt][nt][0], c[mt][nt][1]);
            *(float2*)(C + (size_t)(r0 + 8) * N + cc) =
                make_float2(c[mt][nt][2], c[mt][nt][3]);
        }
    }
}

// ---------------------------------------------------------------------------
// SIGN-FLIPPED interleaved RoPE (rotation by -theta), in-place.  [VERIFIED]
// ---------------------------------------------------------------------------
__global__ void rope_kernel(float* __restrict__ buf, int width)
{
    int idx = blockIdx.x * blockDim.x + threadIdx.x;
    int ppr = width >> 1;
    if (idx >= MROWS * ppr) return;
    int m = idx / ppr;
    int p = idx - m * ppr;
    int i = p & 31;
    int s = m & (SEQ - 1);
    float inv = powf(10000.0f, -((float)(2*i)) / 64.0f);
    float ang = (float)s * inv;
    float c, sn;
    sincosf(ang, &c, &sn);
    sn = -sn;
    float* el = buf + (size_t)m * width + 2*p;
    float xr = el[0], xi = el[1];
    el[0] = xr * c - xi * sn;
    el[1] = xr * sn + xi * c;
}

// ---------------------------------------------------------------------------
// Tensor-core flash attention (tf32 MMA), causal, GQA.
// BM=128, BN=64, 256 threads = 8 warps; warp w owns Q/O rows 16w..16w+15.
// smem: QP[128][68] (Q tf32, then P tf32 — warp-private rows, no sync),
//       K[64][68], V[64][72].  Strides chosen for conflict-free frag loads.
// ---------------------------------------------------------------------------
#define FM_QS 68
#define FM_KS 68
#define FM_VS 72
#define FM_SMEM ((128*FM_QS + 64*FM_KS + 64*FM_VS) * 4)

__global__ __launch_bounds__(256)
void flash_mma(const float* __restrict__ Q, const float* __restrict__ K,
               const float* __restrict__ V, float* __restrict__ O)
{
    extern __shared__ uint32_t smu[];
    uint32_t* qp  = smu;                      // [128][68]  Q -> P
    uint32_t* ksm = smu + 128*FM_QS;          // [64][68]
    uint32_t* vsm = ksm + 64*FM_KS;           // [64][72]

    const int qt = blockIdx.x, h = blockIdx.y, b = blockIdx.z;
    const int kh = h >> 2;                    // NREP = 4
    const int tid  = threadIdx.x;
    const int lane = tid & 31, warp = tid >> 5;
    const int m0 = warp * 16;
    const int lr = lane >> 2, lc = lane & 3;
    const float scale = 0.125f;

    const size_t qrow0 = (size_t)(b*SEQ) + qt*128;

    // ---- load Q tile to smem (tf32) ----
    for (int e = tid; e < 128*16; e += 256) {
        int r = e >> 4, c4 = (e & 15) * 4;
        float4 v4 = *(const float4*)(Q + (qrow0 + r)*D_MODEL + h*HD + c4);
        uint32_t* d = qp + r*FM_QS + c4;
        d[0]=f2tf32(v4.x); d[1]=f2tf32(v4.y); d[2]=f2tf32(v4.z); d[3]=f2tf32(v4.w);
    }
    __syncthreads();

    // ---- Q a-frags to registers (warp-private rows) ----
    uint32_t qa[8][4];
    #pragma unroll
    for (int ks = 0; ks < 8; ks++) {
        int kb = ks * 8;
        qa[ks][0] = qp[(m0+lr  )*FM_QS + kb + lc];
        qa[ks][1] = qp[(m0+lr+8)*FM_QS + kb + lc];
        qa[ks][2] = qp[(m0+lr  )*FM_QS + kb + lc + 4];
        qa[ks][3] = qp[(m0+lr+8)*FM_QS + kb + lc + 4];
    }

    float o[8][4];
    #pragma unroll
    for (int nt = 0; nt < 8; nt++)
        #pragma unroll
        for (int e = 0; e < 4; e++) o[nt][e] = 0.f;
    float mrow0 = -INFINITY, mrow1 = -INFINITY, lrow0 = 0.f, lrow1 = 0.f;

    const int ktmax = 2*qt + 1;
    for (int kt = 0; kt <= ktmax; kt++) {
        // ---- load K,V tiles (tf32) ----
        for (int e = tid; e < 64*16; e += 256) {
            int r = e >> 4, c4 = (e & 15) * 4;
            size_t gi = ((size_t)(b*SEQ) + kt*64 + r) * KVW + kh*HD + c4;
            float4 kv = *(const float4*)(K + gi);
            float4 vv = *(const float4*)(V + gi);
            uint32_t* dk = ksm + r*FM_KS + c4;
            dk[0]=f2tf32(kv.x); dk[1]=f2tf32(kv.y); dk[2]=f2tf32(kv.z); dk[3]=f2tf32(kv.w);
            uint32_t* dv = vsm + r*FM_VS + c4;
            dv[0]=f2tf32(vv.x); dv[1]=f2tf32(vv.y); dv[2]=f2tf32(vv.z); dv[3]=f2tf32(vv.w);
        }
        __syncthreads();

        // ---- S = Q @ K^T ----
        float s[8][4];
        #pragma unroll
        for (int nt = 0; nt < 8; nt++)
            #pragma unroll
            for (int e = 0; e < 4; e++) s[nt][e] = 0.f;

        #pragma unroll
        for (int ks = 0; ks < 8; ks++) {
            int kb = ks * 8;
            uint32_t bf[8][2];
            #pragma unroll
            for (int nt = 0; nt < 8; nt++) {
                bf[nt][0] = ksm[(nt*8 + lr)*FM_KS + kb + lc];
                bf[nt][1] = ksm[(nt*8 + lr)*FM_KS + kb + lc + 4];
            }
            #pragma unroll
            for (int nt = 0; nt < 8; nt++)
                MMA_TF32(s[nt], qa[ks], bf[nt]);
        }

        // ---- scale + causal mask ----
        const bool part = (kt >= 2*qt);
        const int rg0 = qt*128 + m0 + lr;
        const int rg1 = rg0 + 8;
        #pragma unroll
        for (int nt = 0; nt < 8; nt++) {
            int cg = kt*64 + nt*8 + 2*lc;
            s[nt][0] *= scale; s[nt][1] *= scale;
            s[nt][2] *= scale; s[nt][3] *= scale;
            if (part) {
                if (cg     > rg0) s[nt][0] = -INFINITY;
                if (cg + 1 > rg0) s[nt][1] = -INFINITY;
                if (cg     > rg1) s[nt][2] = -INFINITY;
                if (cg + 1 > rg1) s[nt][3] = -INFINITY;
            }
        }

        // ---- online softmax (rows warp-private; reduce over quad lanes) ----
        float mx0 = -INFINITY, mx1 = -INFINITY;
        #pragma unroll
        for (int nt = 0; nt < 8; nt++) {
            mx0 = fmaxf(mx0, fmaxf(s[nt][0], s[nt][1]));
            mx1 = fmaxf(mx1, fmaxf(s[nt][2], s[nt][3]));
        }
        mx0 = fmaxf(mx0, __shfl_xor_sync(0xffffffffu, mx0, 1));
        mx0 = fmaxf(mx0, __shfl_xor_sync(0xffffffffu, mx0, 2));
        mx1 = fmaxf(mx1, __shfl_xor_sync(0xffffffffu, mx1, 1));
        mx1 = fmaxf(mx1, __shfl_xor_sync(0xffffffffu, mx1, 2));

        float mn0 = fmaxf(mrow0, mx0), mn1 = fmaxf(mrow1, mx1);
        float al0 = __expf(mrow0 - mn0), al1 = __expf(mrow1 - mn1);
        float rs0 = 0.f, rs1 = 0.f;
        #pragma unroll
        for (int nt = 0; nt < 8; nt++) {
            s[nt][0] = __expf(s[nt][0] - mn0); rs0 += s[nt][0];
            s[nt][1] = __expf(s[nt][1] - mn0); rs0 += s[nt][1];
            s[nt][2] = __expf(s[nt][2] - mn1); rs1 += s[nt][2];
            s[nt][3] = __expf(s[nt][3] - mn1); rs1 += s[nt][3];
        }
        rs0 += __shfl_xor_sync(0xffffffffu, rs0, 1);
        rs0 += __shfl_xor_sync(0xffffffffu, rs0, 2);
        rs1 += __shfl_xor_sync(0xffffffffu, rs1, 1);
        rs1 += __shfl_xor_sync(0xffffffffu, rs1, 2);
        lrow0 = lrow0 * al0 + rs0; mrow0 = mn0;
        lrow1 = lrow1 * al1 + rs1; mrow1 = mn1;

        #pragma unroll
        for (int nt = 0; nt < 8; nt++) {
            o[nt][0] *= al0; o[nt][1] *= al0;
            o[nt][2] *= al1; o[nt][3] *= al1;
        }

        // ---- write P (tf32) to warp-private rows of qp ----
        #pragma unroll
        for (int nt = 0; nt < 8; nt++) {
            uint32_t* p0 = qp + (m0+lr  )*FM_QS + nt*8 + 2*lc;
            uint32_t* p1 = qp + (m0+lr+8)*FM_QS + nt*8 + 2*lc;
            p0[0] = f2tf32(s[nt][0]); p0[1] = f2tf32(s[nt][1]);
            p1[0] = f2tf32(s[nt][2]); p1[1] = f2tf32(s[nt][3]);
        }

        // ---- O += P @ V ----
        #pragma unroll
        for (int ks = 0; ks < 8; ks++) {
            int kb = ks * 8;
            uint32_t pa[4];
            pa[0] = qp[(m0+lr  )*FM_QS + kb + lc];
            pa[1] = qp[(m0+lr+8)*FM_QS + kb + lc];
            pa[2] = qp[(m0+lr  )*FM_QS + kb + lc + 4];
            pa[3] = qp[(m0+lr+8)*FM_QS + kb + lc + 4];
            uint32_t bf[8][2];
            #pragma unroll
            for (int nt = 0; nt < 8; nt++) {
                bf[nt][0] = vsm[(kb + lc    )*FM_VS + nt*8 + lr];
                bf[nt][1] = vsm[(kb + lc + 4)*FM_VS + nt*8 + lr];
            }
            #pragma unroll
            for (int nt = 0; nt < 8; nt++)
                MMA_TF32(o[nt], pa, bf[nt]);
        }
        __syncthreads();   // protect K/V before next tile load
    }

    // ---- normalize + store ----
    float inv0 = 1.f / lrow0, inv1 = 1.f / lrow1;
    #pragma unroll
    for (int nt = 0; nt < 8; nt++) {
        int cc = h*HD + nt*8 + 2*lc;
        *(float2*)(O + (qrow0 + m0 + lr    )*D_MODEL + cc) =
            make_float2(o[nt][0]*inv0, o[nt][1]*inv0);
        *(float2*)(O + (qrow0 + m0 + lr + 8)*D_MODEL + cc) =
            make_float2(o[nt][2]*inv1, o[nt][3]*inv1);
    }
}

// ---------------------------------------------------------------------------
extern "C" void kernel_launch(void* const* d_in, const int* in_sizes, int n_in,
                              void* d_out, int out_size)
{
    (void)in_sizes; (void)n_in; (void)out_size;
    const float* x  = (const float*)d_in[0];
    const float* wq = (const float*)d_in[1];
    const float* wk = (const float*)d_in[2];
    const float* wv = (const float*)d_in[3];
    const float* wo = (const float*)d_in[4];
    float* out = (float*)d_out;

    float *q, *k, *v, *attn;
    cudaGetSymbolAddress((void**)&q,    g_q);
    cudaGetSymbolAddress((void**)&k,    g_k);
    cudaGetSymbolAddress((void**)&v,    g_v);
    cudaGetSymbolAddress((void**)&attn, g_attn);

    cudaFuncSetAttribute(flash_mma, cudaFuncAttributeMaxDynamicSharedMemorySize,
                         FM_SMEM);

    // projections (tf32 tensor cores)
    gemm_tf32<<<dim3(D_MODEL/128, MROWS/128), 256>>>(x, wq, q, D_MODEL, D_MODEL);
    gemm_tf32<<<dim3(KVW/128,    MROWS/128), 256>>>(x, wk, k, KVW,     D_MODEL);
    gemm_tf32<<<dim3(KVW/128,    MROWS/128), 256>>>(x, wv, v, KVW,     D_MODEL);
    // sign-flipped interleaved rope
    rope_kernel<<<(MROWS*(D_MODEL/2) + 255)/256, 256>>>(q, D_MODEL);
    rope_kernel<<<(MROWS*(KVW/2)    + 255)/256, 256>>>(k, KVW);
    // attention (tf32 tensor cores)
    flash_mma<<<dim3(SEQ/128, NH, NBATCH), 256, FM_SMEM>>>(q, k, v, attn);
    // output projection
    gemm_tf32<<<dim3(D_MODEL/128, MROWS/128), 256>>>(attn, wo, out, D_MODEL, D_MODEL);
}

// round 12
// speedup vs baseline: 3.4982x; 1.3863x over previous
#include <cuda_runtime.h>
#include <math.h>
#include <stdint.h>

#define D_MODEL 2048
#define SEQ     2048
#define NBATCH  2
#define NH      32
#define NKV     8
#define HD      64
#define NREP    4
#define KVW     (NKV*HD)        // 512
#define MROWS   (NBATCH*SEQ)    // 4096

// scratch (static device globals — no allocations allowed)
__device__ float g_q[(size_t)MROWS * D_MODEL];
__device__ float g_k[(size_t)MROWS * KVW];
__device__ float g_v[(size_t)MROWS * KVW];
__device__ float g_attn[(size_t)MROWS * D_MODEL];

__device__ __forceinline__ uint32_t f2tf32(float x) {
    uint32_t r;
    asm("cvt.rna.tf32.f32 %0, %1;" : "=r"(r) : "f"(x));
    return r;
}

#define MMA_TF32(C, A, B)                                                     \
    asm volatile(                                                             \
        "mma.sync.aligned.m16n8k8.row.col.f32.tf32.tf32.f32 "                \
        "{%0,%1,%2,%3}, {%4,%5,%6,%7}, {%8,%9}, {%0,%1,%2,%3};"              \
        : "+f"((C)[0]), "+f"((C)[1]), "+f"((C)[2]), "+f"((C)[3])             \
        : "r"((A)[0]), "r"((A)[1]), "r"((A)[2]), "r"((A)[3]),                \
          "r"((B)[0]), "r"((B)[1]))

__device__ __forceinline__ void cp_async16(uint32_t* smem_dst, const float* gsrc) {
    uint32_t s = (uint32_t)__cvta_generic_to_shared(smem_dst);
    asm volatile("cp.async.cg.shared.global [%0], [%1], 16;\n"
                 :: "r"(s), "l"(gsrc));
}
#define CP_COMMIT() asm volatile("cp.async.commit_group;\n")
#define CP_WAIT1()  asm volatile("cp.async.wait_group 1;\n")

// ---------------------------------------------------------------------------
// Pipelined tf32 GEMM core: C[128 rows][N cols block] = Ab[128][K] @ Bb[128][K]^T
// 2-stage cp.async double buffer, BK=32, 256 threads, 8 warps (2m x 4n).
// smem: raw fp32 bits, [2][128][36]; cvt.rna at frag-load (bit-identical math).
// ---------------------------------------------------------------------------
#define GP_STRIDE 36
#define GP_STAGE  (128*GP_STRIDE)
#define GP_SMEM   (2*GP_STAGE*2*4)      // 73728 bytes

__device__ __forceinline__ void gemm_core(
    const float* __restrict__ Ab, const float* __restrict__ Bb,
    float* __restrict__ C, int N, int cx, int cy, int K)
{
    extern __shared__ uint32_t smp[];
    uint32_t* As = smp;                  // [2][128][36]
    uint32_t* Bs = smp + 2*GP_STAGE;

    const int tid  = threadIdx.x;
    const int lane = tid & 31, warp = tid >> 5;
    const int wm = (warp & 1) * 64, wn = (warp >> 1) * 32;
    const int lr = lane >> 2,  lc = lane & 3;

    float acc[4][4][4];
    #pragma unroll
    for (int mt = 0; mt < 4; mt++)
        #pragma unroll
        for (int nt = 0; nt < 4; nt++)
            #pragma unroll
            for (int e = 0; e < 4; e++) acc[mt][nt][e] = 0.f;

    // chunk c = tid + i*256 (0..1023): row = c>>3, kc = (c&7)*4
    #pragma unroll
    for (int st = 0; st < 2; st++) {
        #pragma unroll
        for (int i = 0; i < 4; i++) {
            int ch = tid + i*256;
            int row = ch >> 3, kc = (ch & 7) * 4;
            cp_async16(As + st*GP_STAGE + row*GP_STRIDE + kc,
                       Ab + (size_t)row*K + st*32 + kc);
            cp_async16(Bs + st*GP_STAGE + row*GP_STRIDE + kc,
                       Bb + (size_t)row*K + st*32 + kc);
        }
        CP_COMMIT();
    }
    CP_WAIT1();
    __syncthreads();

    const int niter = K / 32;
    for (int it = 0; it < niter; it++) {
        const float* Ac = (const float*)(As + (it & 1)*GP_STAGE);
        const float* Bc = (const float*)(Bs + (it & 1)*GP_STAGE);

        #pragma unroll
        for (int ks = 0; ks < 4; ks++) {
            const int kb = ks * 8;
            uint32_t af[4][4], bf[4][2];
            #pragma unroll
            for (int mt = 0; mt < 4; mt++) {
                int r0 = wm + mt*16 + lr;
                af[mt][0] = f2tf32(Ac[(r0    )*GP_STRIDE + kb + lc]);
                af[mt][1] = f2tf32(Ac[(r0 + 8)*GP_STRIDE + kb + lc]);
                af[mt][2] = f2tf32(Ac[(r0    )*GP_STRIDE + kb + lc + 4]);
                af[mt][3] = f2tf32(Ac[(r0 + 8)*GP_STRIDE + kb + lc + 4]);
            }
            #pragma unroll
            for (int nt = 0; nt < 4; nt++) {
                int n0 = wn + nt*8 + lr;
                bf[nt][0] = f2tf32(Bc[n0*GP_STRIDE + kb + lc]);
                bf[nt][1] = f2tf32(Bc[n0*GP_STRIDE + kb + lc + 4]);
            }
            #pragma unroll
            for (int mt = 0; mt < 4; mt++)
                #pragma unroll
                for (int nt = 0; nt < 4; nt++)
                    MMA_TF32(acc[mt][nt], af[mt], bf[nt]);
        }
        __syncthreads();                 // all warps done reading this stage

        if (it + 2 < niter) {
            int k0 = (it + 2) * 32;
            int st = it & 1;
            #pragma unroll
            for (int i = 0; i < 4; i++) {
                int ch = tid + i*256;
                int row = ch >> 3, kc = (ch & 7) * 4;
                cp_async16(As + st*GP_STAGE + row*GP_STRIDE + kc,
                           Ab + (size_t)row*K + k0 + kc);
                cp_async16(Bs + st*GP_STAGE + row*GP_STRIDE + kc,
                           Bb + (size_t)row*K + k0 + kc);
            }
        }
        CP_COMMIT();
        CP_WAIT1();
        __syncthreads();
    }

    #pragma unroll
    for (int mt = 0; mt < 4; mt++) {
        int r0 = cy + wm + mt*16 + lr;
        #pragma unroll
        for (int nt = 0; nt < 4; nt++) {
            int cc = cx + wn + nt*8 + lc*2;
            *(float2*)(C + (size_t)r0 * N + cc) =
                make_float2(acc[mt][nt][0], acc[mt][nt][1]);
            *(float2*)(C + (size_t)(r0 + 8) * N + cc) =
                make_float2(acc[mt][nt][2], acc[mt][nt][3]);
        }
    }
}

// Fused q/k/v projections: grid (24, MROWS/128).  bx<16 -> q, <20 -> k, else v
__global__ __launch_bounds__(256)
void gemm_qkv(const float* __restrict__ x,
              const float* __restrict__ wq, const float* __restrict__ wk,
              const float* __restrict__ wv,
              float* __restrict__ q, float* __restrict__ k, float* __restrict__ v)
{
    const int bx = blockIdx.x, by = blockIdx.y;
    const float* Ab = x + (size_t)by * 128 * D_MODEL;
    const float* Bb; float* C; int N, cx;
    if (bx < 16)      { Bb = wq + (size_t)bx*128*D_MODEL;      C = q; N = D_MODEL; cx = bx*128; }
    else if (bx < 20) { Bb = wk + (size_t)(bx-16)*128*D_MODEL; C = k; N = KVW;     cx = (bx-16)*128; }
    else              { Bb = wv + (size_t)(bx-20)*128*D_MODEL; C = v; N = KVW;     cx = (bx-20)*128; }
    gemm_core(Ab, Bb, C, N, cx, by*128, D_MODEL);
}

// Plain pipelined GEMM: C[M,N] = A[M,K] @ B[N,K]^T
__global__ __launch_bounds__(256)
void gemm_tf32p(const float* __restrict__ A, const float* __restrict__ B,
                float* __restrict__ C, int N, int K)
{
    gemm_core(A + (size_t)blockIdx.y*128*K, B + (size_t)blockIdx.x*128*K,
              C, N, blockIdx.x*128, blockIdx.y*128, K);
}

// ---------------------------------------------------------------------------
// SIGN-FLIPPED interleaved RoPE (rotation by -theta), in-place.  [VERIFIED]
// ---------------------------------------------------------------------------
__global__ void rope_kernel(float* __restrict__ buf, int width)
{
    int idx = blockIdx.x * blockDim.x + threadIdx.x;
    int ppr = width >> 1;
    if (idx >= MROWS * ppr) return;
    int m = idx / ppr;
    int p = idx - m * ppr;
    int i = p & 31;
    int s = m & (SEQ - 1);
    float inv = powf(10000.0f, -((float)(2*i)) / 64.0f);
    float ang = (float)s * inv;
    float c, sn;
    sincosf(ang, &c, &sn);
    sn = -sn;
    float* el = buf + (size_t)m * width + 2*p;
    float xr = el[0], xi = el[1];
    el[0] = xr * c - xi * sn;
    el[1] = xr * sn + xi * c;
}

// ---------------------------------------------------------------------------
// Tensor-core flash attention (tf32 MMA), causal, GQA.  [R10, VERIFIED]
// ---------------------------------------------------------------------------
#define FM_QS 68
#define FM_KS 68
#define FM_VS 72
#define FM_SMEM ((128*FM_QS + 64*FM_KS + 64*FM_VS) * 4)

__global__ __launch_bounds__(256)
void flash_mma(const float* __restrict__ Q, const float* __restrict__ K,
               const float* __restrict__ V, float* __restrict__ O)
{
    extern __shared__ uint32_t smu[];
    uint32_t* qp  = smu;
    uint32_t* ksm = smu + 128*FM_QS;
    uint32_t* vsm = ksm + 64*FM_KS;

    const int qt = blockIdx.x, h = blockIdx.y, b = blockIdx.z;
    const int kh = h >> 2;
    const int tid  = threadIdx.x;
    const int lane = tid & 31, warp = tid >> 5;
    const int m0 = warp * 16;
    const int lr = lane >> 2, lc = lane & 3;
    const float scale = 0.125f;

    const size_t qrow0 = (size_t)(b*SEQ) + qt*128;

    for (int e = tid; e < 128*16; e += 256) {
        int r = e >> 4, c4 = (e & 15) * 4;
        float4 v4 = *(const float4*)(Q + (qrow0 + r)*D_MODEL + h*HD + c4);
        uint32_t* d = qp + r*FM_QS + c4;
        d[0]=f2tf32(v4.x); d[1]=f2tf32(v4.y); d[2]=f2tf32(v4.z); d[3]=f2tf32(v4.w);
    }
    __syncthreads();

    uint32_t qa[8][4];
    #pragma unroll
    for (int ks = 0; ks < 8; ks++) {
        int kb = ks * 8;
        qa[ks][0] = qp[(m0+lr  )*FM_QS + kb + lc];
        qa[ks][1] = qp[(m0+lr+8)*FM_QS + kb + lc];
        qa[ks][2] = qp[(m0+lr  )*FM_QS + kb + lc + 4];
        qa[ks][3] = qp[(m0+lr+8)*FM_QS + kb + lc + 4];
    }

    float o[8][4];
    #pragma unroll
    for (int nt = 0; nt < 8; nt++)
        #pragma unroll
        for (int e = 0; e < 4; e++) o[nt][e] = 0.f;
    float mrow0 = -INFINITY, mrow1 = -INFINITY, lrow0 = 0.f, lrow1 = 0.f;

    const int ktmax = 2*qt + 1;
    for (int kt = 0; kt <= ktmax; kt++) {
        for (int e = tid; e < 64*16; e += 256) {
            int r = e >> 4, c4 = (e & 15) * 4;
            size_t gi = ((size_t)(b*SEQ) + kt*64 + r) * KVW + kh*HD + c4;
            float4 kv = *(const float4*)(K + gi);
            float4 vv = *(const float4*)(V + gi);
            uint32_t* dk = ksm + r*FM_KS + c4;
            dk[0]=f2tf32(kv.x); dk[1]=f2tf32(kv.y); dk[2]=f2tf32(kv.z); dk[3]=f2tf32(kv.w);
            uint32_t* dv = vsm + r*FM_VS + c4;
            dv[0]=f2tf32(vv.x); dv[1]=f2tf32(vv.y); dv[2]=f2tf32(vv.z); dv[3]=f2tf32(vv.w);
        }
        __syncthreads();

        float s[8][4];
        #pragma unroll
        for (int nt = 0; nt < 8; nt++)
            #pragma unroll
            for (int e = 0; e < 4; e++) s[nt][e] = 0.f;

        #pragma unroll
        for (int ks = 0; ks < 8; ks++) {
            int kb = ks * 8;
            uint32_t bf[8][2];
            #pragma unroll
            for (int nt = 0; nt < 8; nt++) {
                bf[nt][0] = ksm[(nt*8 + lr)*FM_KS + kb + lc];
                bf[nt][1] = ksm[(nt*8 + lr)*FM_KS + kb + lc + 4];
            }
            #pragma unroll
            for (int nt = 0; nt < 8; nt++)
                MMA_TF32(s[nt], qa[ks], bf[nt]);
        }

        const bool part = (kt >= 2*qt);
        const int rg0 = qt*128 + m0 + lr;
        const int rg1 = rg0 + 8;
        #pragma unroll
        for (int nt = 0; nt < 8; nt++) {
            int cg = kt*64 + nt*8 + 2*lc;
            s[nt][0] *= scale; s[nt][1] *= scale;
            s[nt][2] *= scale; s[nt][3] *= scale;
            if (part) {
                if (cg     > rg0) s[nt][0] = -INFINITY;
                if (cg + 1 > rg0) s[nt][1] = -INFINITY;
                if (cg     > rg1) s[nt][2] = -INFINITY;
                if (cg + 1 > rg1) s[nt][3] = -INFINITY;
            }
        }

        float mx0 = -INFINITY, mx1 = -INFINITY;
        #pragma unroll
        for (int nt = 0; nt < 8; nt++) {
            mx0 = fmaxf(mx0, fmaxf(s[nt][0], s[nt][1]));
            mx1 = fmaxf(mx1, fmaxf(s[nt][2], s[nt][3]));
        }
        mx0 = fmaxf(mx0, __shfl_xor_sync(0xffffffffu, mx0, 1));
        mx0 = fmaxf(mx0, __shfl_xor_sync(0xffffffffu, mx0, 2));
        mx1 = fmaxf(mx1, __shfl_xor_sync(0xffffffffu, mx1, 1));
        mx1 = fmaxf(mx1, __shfl_xor_sync(0xffffffffu, mx1, 2));

        float mn0 = fmaxf(mrow0, mx0), mn1 = fmaxf(mrow1, mx1);
        float al0 = __expf(mrow0 - mn0), al1 = __expf(mrow1 - mn1);
        float rs0 = 0.f, rs1 = 0.f;
        #pragma unroll
        for (int nt = 0; nt < 8; nt++) {
            s[nt][0] = __expf(s[nt][0] - mn0); rs0 += s[nt][0];
            s[nt][1] = __expf(s[nt][1] - mn0); rs0 += s[nt][1];
            s[nt][2] = __expf(s[nt][2] - mn1); rs1 += s[nt][2];
            s[nt][3] = __expf(s[nt][3] - mn1); rs1 += s[nt][3];
        }
        rs0 += __shfl_xor_sync(0xffffffffu, rs0, 1);
        rs0 += __shfl_xor_sync(0xffffffffu, rs0, 2);
        rs1 += __shfl_xor_sync(0xffffffffu, rs1, 1);
        rs1 += __shfl_xor_sync(0xffffffffu, rs1, 2);
        lrow0 = lrow0 * al0 + rs0; mrow0 = mn0;
        lrow1 = lrow1 * al1 + rs1; mrow1 = mn1;

        #pragma unroll
        for (int nt = 0; nt < 8; nt++) {
            o[nt][0] *= al0; o[nt][1] *= al0;
            o[nt][2] *= al1; o[nt][3] *= al1;
        }

        #pragma unroll
        for (int nt = 0; nt < 8; nt++) {
            uint32_t* p0 = qp + (m0+lr  )*FM_QS + nt*8 + 2*lc;
            uint32_t* p1 = qp + (m0+lr+8)*FM_QS + nt*8 + 2*lc;
            p0[0] = f2tf32(s[nt][0]); p0[1] = f2tf32(s[nt][1]);
            p1[0] = f2tf32(s[nt][2]); p1[1] = f2tf32(s[nt][3]);
        }

        #pragma unroll
        for (int ks = 0; ks < 8; ks++) {
            int kb = ks * 8;
            uint32_t pa[4];
            pa[0] = qp[(m0+lr  )*FM_QS + kb + lc];
            pa[1] = qp[(m0+lr+8)*FM_QS + kb + lc];
            pa[2] = qp[(m0+lr  )*FM_QS + kb + lc + 4];
            pa[3] = qp[(m0+lr+8)*FM_QS + kb + lc + 4];
            uint32_t bf[8][2];
            #pragma unroll
            for (int nt = 0; nt < 8; nt++) {
                bf[nt][0] = vsm[(kb + lc    )*FM_VS + nt*8 + lr];
                bf[nt][1] = vsm[(kb + lc + 4)*FM_VS + nt*8 + lr];
            }
            #pragma unroll
            for (int nt = 0; nt < 8; nt++)
                MMA_TF32(o[nt], pa, bf[nt]);
        }
        __syncthreads();
    }

    float inv0 = 1.f / lrow0, inv1 = 1.f / lrow1;
    #pragma unroll
    for (int nt = 0; nt < 8; nt++) {
        int cc = h*HD + nt*8 + 2*lc;
        *(float2*)(O + (qrow0 + m0 + lr    )*D_MODEL + cc) =
            make_float2(o[nt][0]*inv0, o[nt][1]*inv0);
        *(float2*)(O + (qrow0 + m0 + lr + 8)*D_MODEL + cc) =
            make_float2(o[nt][2]*inv1, o[nt][3]*inv1);
    }
}

// ---------------------------------------------------------------------------
extern "C" void kernel_launch(void* const* d_in, const int* in_sizes, int n_in,
                              void* d_out, int out_size)
{
    (void)in_sizes; (void)n_in; (void)out_size;
    const float* x  = (const float*)d_in[0];
    const float* wq = (const float*)d_in[1];
    const float* wk = (const float*)d_in[2];
    const float* wv = (const float*)d_in[3];
    const float* wo = (const float*)d_in[4];
    float* out = (float*)d_out;

    float *q, *k, *v, *attn;
    cudaGetSymbolAddress((void**)&q,    g_q);
    cudaGetSymbolAddress((void**)&k,    g_k);
    cudaGetSymbolAddress((void**)&v,    g_v);
    cudaGetSymbolAddress((void**)&attn, g_attn);

    cudaFuncSetAttribute(flash_mma, cudaFuncAttributeMaxDynamicSharedMemorySize, FM_SMEM);
    cudaFuncSetAttribute(gemm_qkv,  cudaFuncAttributeMaxDynamicSharedMemorySize, GP_SMEM);
    cudaFuncSetAttribute(gemm_tf32p,cudaFuncAttributeMaxDynamicSharedMemorySize, GP_SMEM);

    // fused q/k/v projections (pipelined tf32)
    gemm_qkv<<<dim3(24, MROWS/128), 256, GP_SMEM>>>(x, wq, wk, wv, q, k, v);
    // sign-flipped interleaved rope
    rope_kernel<<<(MROWS*(D_MODEL/2) + 255)/256, 256>>>(q, D_MODEL);
    rope_kernel<<<(MROWS*(KVW/2)    + 255)/256, 256>>>(k, KVW);
    // attention (tf32 tensor cores)
    flash_mma<<<dim3(SEQ/128, NH, NBATCH), 256, FM_SMEM>>>(q, k, v, attn);
    // output projection (pipelined tf32)
    gemm_tf32p<<<dim3(D_MODEL/128, MROWS/128), 256, GP_SMEM>>>(attn, wo, out, D_MODEL, D_MODEL);
}